// round 17
// baseline (speedup 1.0000x reference)
#include <cuda_runtime.h>

// SSIM loss, vertical-first separable blur — R4 scalar engine with
// BRANCH-FREE V-phase slot trims:
//   * rows gy in [y0, y0+15] are valid for EVERY block -> bare LDG with
//     compile-time immediate offsets (no bounds / clamp / select), uniformly.
//   * only the 5 top-halo + 5 bottom-halo rows keep clamp+select (uniform y).
//   * x-OOB threads point at a static zero plane -> no per-row x selects.
//   H: 4 px/thread, conflict-free float4 smem reads, imm-form FFMA taps,
//      scalar SSIM + fast divide; fused deterministic mean.
// Inputs: 2x [16,3,512,512] fp32. Output: 1 fp32 scalar.

#define NTHR    160
#define TILE_W  128
#define TILE_H  16
#define RAD     5
#define KW      11
#define VCOLS   (TILE_W + 2 * RAD)   // 138
#define VSTRIDE 140                  // floats per row, 16B aligned
#define HH      512
#define WW      512
#define PLANES  48
#define GX      (WW / TILE_W)        // 4
#define GY      (HH / TILE_H)        // 32
#define NBLK    (GX * GY * PLANES)   // 6144

__device__ float        g_partials[NBLK];
__device__ unsigned int g_count = 0;
__device__ float        g_zplane[HH * WW];   // static zeros: x-OOB read target

// Gaussian(sigma=1.5) 11 taps, normalized; literals -> immediate-form FFMA.
__device__ __forceinline__ constexpr float GW(int k) {
    return (k == 0 || k == 10) ? 0.00102838f
         : (k == 1 || k == 9)  ? 0.00759877f
         : (k == 2 || k == 8)  ? 0.03600075f
         : (k == 3 || k == 7)  ? 0.10936082f
         : (k == 4 || k == 6)  ? 0.21300554f
         :                       0.26601172f;
}

__global__ void __launch_bounds__(NTHR, 5)
ssim_main(const float* __restrict__ img1, const float* __restrict__ img2,
          float* __restrict__ out)
{
    // SoA field buffers: [field][row][col], rows 16B-aligned.
    __shared__ __align__(16) float smf[4][TILE_H][VSTRIDE];

    const int tid   = threadIdx.x;
    const int x0    = blockIdx.x * TILE_W;
    const int y0    = blockIdx.y * TILE_H;
    const int plane = blockIdx.z;
    const size_t pbase = (size_t)plane * (HH * WW);

    // ================= Vertical phase =================
    if (tid < VCOLS) {
        const int gx  = x0 + tid - RAD;
        const bool vx = ((unsigned)gx < WW);
        // x-OOB threads read the zero plane (no per-row selects needed).
        const float* __restrict__ r1 =
            (vx ? img1 + pbase + gx : g_zplane) + (size_t)y0 * WW;
        const float* __restrict__ r2 =
            (vx ? img2 + pbase + gx : g_zplane) + (size_t)y0 * WW;

        float ra[KW], rb[KW], rs[KW], rp[KW];

        // Row i maps to gy = y0 + i - RAD. i in [5,20] is ALWAYS in-bounds.
        auto loadrow = [&](int i, float& a, float& b) {
            if (i >= RAD && i <= RAD + TILE_H - 1) {
                // interior: bare LDG with compile-time offset
                a = __ldg(r1 + (i - RAD) * WW);
                b = __ldg(r2 + (i - RAD) * WW);
            } else if (i < RAD) {
                // top halo: may underflow (only when y0 == 0)
                int gy  = y0 + i - RAD;
                bool ok = (gy >= 0);
                int ro  = max(gy, 0) - y0;           // in [-5, 0]
                float av = __ldg(r1 + ro * WW);
                float bv = __ldg(r2 + ro * WW);
                a = ok ? av : 0.f;
                b = ok ? bv : 0.f;
            } else {
                // bottom halo: may overflow (only when y0 == 496)
                int gy  = y0 + i - RAD;
                bool ok = (gy < HH);
                int ro  = min(gy, HH - 1) - y0;      // in [16, 20]
                float av = __ldg(r1 + ro * WW);
                float bv = __ldg(r2 + ro * WW);
                a = ok ? av : 0.f;
                b = ok ? bv : 0.f;
            }
        };

        #pragma unroll
        for (int i = 0; i < KW - 1; ++i) {
            float a, b; loadrow(i, a, b);
            ra[i] = a; rb[i] = b;
            rs[i] = fmaf(b, b, a * a);
            rp[i] = a * b;
        }
        float ca, cb;
        loadrow(KW - 1, ca, cb);   // row index 10

        #pragma unroll
        for (int u = 0; u < TILE_H; ++u) {
            const int sl = (u + KW - 1) % KW;
            ra[sl] = ca; rb[sl] = cb;
            rs[sl] = fmaf(cb, cb, ca * ca);
            rp[sl] = ca * cb;
            if (u < TILE_H - 1) loadrow(u + KW, ca, cb);   // interleaved prefetch

            float m1 = 0.f, m2 = 0.f, qs = 0.f, q12 = 0.f;
            #pragma unroll
            for (int j = 0; j < KW; ++j) {
                const int s = (u + j) % KW;      // compile-time
                m1  = fmaf(GW(j), ra[s], m1);
                m2  = fmaf(GW(j), rb[s], m2);
                qs  = fmaf(GW(j), rs[s], qs);
                q12 = fmaf(GW(j), rp[s], q12);
            }
            smf[0][u][tid] = m1;
            smf[1][u][tid] = m2;
            smf[2][u][tid] = qs;
            smf[3][u][tid] = q12;
        }
    }
    __syncthreads();

    // ================= Horizontal + SSIM phase (R4 exact) =================
    float acc = 0.f;
    if (tid < 128) {
        const int cg = tid & 31;    // output cols 4cg..4cg+3
        const int rg = tid >> 5;    // row slot

        #pragma unroll 1
        for (int rr = 0; rr < 4; ++rr) {
            const int r = rr * 4 + rg;

            float fm1[4], fm2[4], fqs[4], fq12[4];
            #pragma unroll
            for (int d = 0; d < 4; ++d) { fm1[d] = fm2[d] = fqs[d] = fq12[d] = 0.f; }

            // Per field: 4 float4 loads cover cols 4cg..4cg+15 (need ..+13).
            #pragma unroll
            for (int f = 0; f < 4; ++f) {
                const float4* __restrict__ rp4 =
                    reinterpret_cast<const float4*>(&smf[f][r][0]);
                float4 q0 = rp4[cg + 0];
                float4 q1 = rp4[cg + 1];
                float4 q2 = rp4[cg + 2];
                float4 q3 = rp4[cg + 3];
                float cv[16] = { q0.x, q0.y, q0.z, q0.w,
                                 q1.x, q1.y, q1.z, q1.w,
                                 q2.x, q2.y, q2.z, q2.w,
                                 q3.x, q3.y, q3.z, q3.w };
                float* dst = (f == 0) ? fm1 : (f == 1) ? fm2 : (f == 2) ? fqs : fq12;
                #pragma unroll
                for (int d = 0; d < 4; ++d) {
                    float a = 0.f;
                    #pragma unroll
                    for (int k = 0; k < KW; ++k)
                        a = fmaf(GW(k), cv[d + k], a);
                    dst[d] = a;
                }
            }

            #pragma unroll
            for (int d = 0; d < 4; ++d) {
                float mu12 = fm1[d] * fm2[d];
                float mu1s = fm1[d] * fm1[d];
                float mu2s = fm2[d] * fm2[d];
                float s12  = fq12[d] - mu12;
                float n1   = fmaf(2.f, mu12, 1e-4f);
                float n2   = fmaf(2.f, s12,  9e-4f);
                float ttv  = mu1s + mu2s;
                float d1   = ttv + 1e-4f;
                float d2   = (fqs[d] - ttv) + 9e-4f;
                acc += __fdividef(n1 * n2, d1 * d2);
            }
        }
    }

    // ================= Reduction =================
    #pragma unroll
    for (int o = 16; o; o >>= 1)
        acc += __shfl_xor_sync(0xFFFFFFFFu, acc, o);

    __shared__ float ws[NTHR / 32];
    if ((tid & 31) == 0) ws[tid >> 5] = acc;
    __syncthreads();

    const int bid = (blockIdx.z * GY + blockIdx.y) * GX + blockIdx.x;
    __shared__ unsigned int is_last;
    if (tid == 0) {
        float bs = 0.f;
        #pragma unroll
        for (int i = 0; i < NTHR / 32; ++i) bs += ws[i];
        __stcg(&g_partials[bid], bs);
        __threadfence();
        is_last = (atomicAdd(&g_count, 1u) == (unsigned)(NBLK - 1));
    }
    __syncthreads();

    if (is_last) {
        double s = 0.0;
        for (int i = tid; i < NBLK; i += NTHR)
            s += (double)__ldcg(&g_partials[i]);
        #pragma unroll
        for (int o = 16; o; o >>= 1)
            s += __shfl_xor_sync(0xFFFFFFFFu, s, o);
        __shared__ double wd[NTHR / 32];
        if ((tid & 31) == 0) wd[tid >> 5] = s;
        __syncthreads();
        if (tid == 0) {
            double bs = 0.0;
            #pragma unroll
            for (int i = 0; i < NTHR / 32; ++i) bs += wd[i];
            double n = (double)PLANES * HH * WW;
            out[0] = (float)(1.0 - bs / n);
            g_count = 0;   // reset for next graph replay
        }
    }
}

extern "C" void kernel_launch(void* const* d_in, const int* in_sizes, int n_in,
                              void* d_out, int out_size)
{
    (void)in_sizes; (void)n_in; (void)out_size;
    const float* img1 = (const float*)d_in[0];
    const float* img2 = (const float*)d_in[1];
    float* out = (float*)d_out;

    dim3 grid(GX, GY, PLANES);
    ssim_main<<<grid, NTHR>>>(img1, img2, out);
}